// round 2
// baseline (speedup 1.0000x reference)
#include <cuda_runtime.h>
#include <stdint.h>

// Problem constants
#define B      128
#define D      512
#define M      262144
#define K_TOP  256

// Output layout: [topk_feat | topk_score | topk_index(as float)]
#define FEAT_ELEMS  ((size_t)B * K_TOP * D)
#define SCORE_OFF   FEAT_ELEMS
#define IDX_OFF     (FEAT_ELEMS + (size_t)B * K_TOP)

typedef unsigned long long ull;

// Scratch
__device__ float g_qn[B * D];
__device__ float g_scores[(size_t)B * M];     // 128 MB
__device__ int   g_topk_idx[B * K_TOP];

// ---------------------------------------------------------------------------
// f32x2 packed helpers (FFMA2 is only reachable via PTX fma.rn.f32x2)
// ---------------------------------------------------------------------------
__device__ __forceinline__ ull pack2(float lo, float hi) {
    ull r; asm("mov.b64 %0, {%1, %2};" : "=l"(r) : "f"(lo), "f"(hi)); return r;
}
__device__ __forceinline__ void unpack2(ull v, float& lo, float& hi) {
    asm("mov.b64 {%0, %1}, %2;" : "=f"(lo), "=f"(hi) : "l"(v));
}
__device__ __forceinline__ ull ffma2(ull a, ull b, ull c) {
    ull d; asm("fma.rn.f32x2 %0, %1, %2, %3;" : "=l"(d) : "l"(a), "l"(b), "l"(c));
    return d;
}

// ---------------------------------------------------------------------------
// Kernel 1: L2-normalize query rows
// ---------------------------------------------------------------------------
__global__ void normalize_kernel(const float* __restrict__ q) {
    int b = blockIdx.x;
    int tid = threadIdx.x;  // 128 threads
    const float* row = q + b * D;
    float s = 0.f;
    for (int i = tid; i < D; i += 128) {
        float v = row[i];
        s += v * v;
    }
    #pragma unroll
    for (int o = 16; o > 0; o >>= 1) s += __shfl_xor_sync(0xffffffffu, s, o);
    __shared__ float ws[4];
    if ((tid & 31) == 0) ws[tid >> 5] = s;
    __syncthreads();
    float tot = ws[0] + ws[1] + ws[2] + ws[3];
    float inv = rsqrtf(tot);
    for (int i = tid; i < D; i += 128) g_qn[b * D + i] = row[i] * inv;
}

// ---------------------------------------------------------------------------
// Kernel 2: fp32 SGEMM via packed FFMA2.
// Tile 128(M) x 128(B) x 16(K), 256 threads, 8 b x 8 m per thread (as 8x4 f32x2).
// Q tile stored in smem as duplicated-half f32x2 so inner loop is LDS + FFMA2.
// ---------------------------------------------------------------------------
#define TM 128
#define TK 16

__global__ __launch_bounds__(256) void gemm_kernel(const float* __restrict__ sk) {
    __shared__ float sK[TK][TM + 4];    // sK[k][m]
    __shared__ ull   sQ2[TK][B + 2];    // sQ2[k][b] = (q, q)

    const int m0 = blockIdx.x * TM;
    const int tid = threadIdx.x;
    const int tx = tid & 15;    // m / 8
    const int ty = tid >> 4;    // b / 8

    ull acc2[8][4];
    const ull z = 0ull;
    #pragma unroll
    for (int i = 0; i < 8; i++)
        #pragma unroll
        for (int j = 0; j < 4; j++) acc2[i][j] = z;

    for (int k0 = 0; k0 < D; k0 += TK) {
        // SK tile: 128 rows x 16 k = 512 float4; 2 per thread
        #pragma unroll
        for (int it = 0; it < 2; it++) {
            int i = tid + it * 256;
            int row = i >> 2;
            int c4  = i & 3;
            float4 v = *(const float4*)(sk + (size_t)(m0 + row) * D + k0 + c4 * 4);
            sK[c4 * 4 + 0][row] = v.x;
            sK[c4 * 4 + 1][row] = v.y;
            sK[c4 * 4 + 2][row] = v.z;
            sK[c4 * 4 + 3][row] = v.w;
        }
        // Q tile: 128 rows x 16 k, packed duplicated halves
        #pragma unroll
        for (int it = 0; it < 2; it++) {
            int i = tid + it * 256;
            int row = i >> 2;
            int c4  = i & 3;
            float4 v = *(const float4*)(g_qn + row * D + k0 + c4 * 4);
            sQ2[c4 * 4 + 0][row] = pack2(v.x, v.x);
            sQ2[c4 * 4 + 1][row] = pack2(v.y, v.y);
            sQ2[c4 * 4 + 2][row] = pack2(v.z, v.z);
            sQ2[c4 * 4 + 3][row] = pack2(v.w, v.w);
        }
        __syncthreads();

        #pragma unroll
        for (int kk = 0; kk < TK; kk++) {
            ull fm2[4], fb2[8];
            const ull* pm = (const ull*)&sK[kk][tx * 8];
            #pragma unroll
            for (int j = 0; j < 4; j++) fm2[j] = pm[j];
            const ull* pb = &sQ2[kk][ty * 8];
            #pragma unroll
            for (int i = 0; i < 8; i++) fb2[i] = pb[i];
            #pragma unroll
            for (int bi = 0; bi < 8; bi++)
                #pragma unroll
                for (int mj = 0; mj < 4; mj++)
                    acc2[bi][mj] = ffma2(fb2[bi], fm2[mj], acc2[bi][mj]);
        }
        __syncthreads();
    }

    // Store: acc2[bi][mj] holds scores for m = m0 + tx*8 + 2*mj (+0 lo, +1 hi)
    #pragma unroll
    for (int bi = 0; bi < 8; bi++) {
        int b = ty * 8 + bi;
        ull* dst = (ull*)(g_scores + (size_t)b * M + m0 + tx * 8);
        ulonglong2 v0; v0.x = acc2[bi][0]; v0.y = acc2[bi][1];
        ulonglong2 v1; v1.x = acc2[bi][2]; v1.y = acc2[bi][3];
        *(ulonglong2*)(dst + 0) = v0;
        *(ulonglong2*)(dst + 2) = v1;
    }
}

// ---------------------------------------------------------------------------
// Kernel 3: per-row exact top-256.
// Pass 1: 2048-bin histogram of top-11 monotone bits + suffix scan -> threshold.
// (conditional 11-bit refine if candidate count > 2048 — practically never)
// Pass 2: collect all candidates >= threshold, bitonic-sort 2048, emit 256.
// ---------------------------------------------------------------------------
__device__ __forceinline__ unsigned mono(float f) {
    unsigned b = __float_as_uint(f);
    return (b & 0x80000000u) ? ~b : (b | 0x80000000u);
}
__device__ __forceinline__ float inv_mono(unsigned u) {
    unsigned b = (u & 0x80000000u) ? (u & 0x7FFFFFFFu) : ~u;
    return __uint_as_float(b);
}

#define NT  1024
#define CAP 2048

__global__ __launch_bounds__(NT) void topk_kernel(float* __restrict__ out) {
    const int b = blockIdx.x;
    const int tid = threadIdx.x;
    const float* row = g_scores + (size_t)b * M;

    __shared__ unsigned s_h[2048];
    __shared__ ull      keys[CAP];
    __shared__ int      s_bin;
    __shared__ unsigned s_above, s_total, s_cnt;

    // ---- Pass 1: 11-bit histogram over top bits of monotone key
    s_h[tid] = 0; s_h[tid + 1024] = 0;
    __syncthreads();
    for (int i = tid; i < M; i += NT) {
        unsigned u = mono(row[i]);
        atomicAdd(&s_h[u >> 21], 1u);
    }
    __syncthreads();
    // suffix inclusive scan (Hillis-Steele), each thread owns bins tid, tid+1024
    for (int off = 1; off < 2048; off <<= 1) {
        unsigned v0 = s_h[tid] + ((tid + off < 2048) ? s_h[tid + off] : 0u);
        int j = tid + 1024;
        unsigned v1 = s_h[j] + ((j + off < 2048) ? s_h[j + off] : 0u);
        __syncthreads();
        s_h[tid] = v0; s_h[j] = v1;
        __syncthreads();
    }
    // find bin: sfx[bin] >= K, sfx[bin+1] < K
    #pragma unroll
    for (int t = 0; t < 2; t++) {
        int j = tid + t * 1024;
        unsigned sj  = s_h[j];
        unsigned sj1 = (j < 2047) ? s_h[j + 1] : 0u;
        if (sj >= K_TOP && sj1 < K_TOP) {
            s_bin = j; s_above = sj1; s_total = sj;
        }
    }
    __syncthreads();

    unsigned thr   = (unsigned)s_bin << 21;
    unsigned total = s_total;
    unsigned above = s_above;
    __syncthreads();

    // ---- Optional refine (next 11 bits) if too many candidates
    if (total > CAP) {
        unsigned coarse = thr >> 21;
        unsigned r1 = K_TOP - above;
        s_h[tid] = 0; s_h[tid + 1024] = 0;
        __syncthreads();
        for (int i = tid; i < M; i += NT) {
            unsigned u = mono(row[i]);
            if ((u >> 21) == coarse) atomicAdd(&s_h[(u >> 10) & 2047u], 1u);
        }
        __syncthreads();
        for (int off = 1; off < 2048; off <<= 1) {
            unsigned v0 = s_h[tid] + ((tid + off < 2048) ? s_h[tid + off] : 0u);
            int j = tid + 1024;
            unsigned v1 = s_h[j] + ((j + off < 2048) ? s_h[j + off] : 0u);
            __syncthreads();
            s_h[tid] = v0; s_h[j] = v1;
            __syncthreads();
        }
        #pragma unroll
        for (int t = 0; t < 2; t++) {
            int j = tid + t * 1024;
            unsigned sj  = s_h[j];
            unsigned sj1 = (j < 2047) ? s_h[j + 1] : 0u;
            if (sj >= r1 && sj1 < r1) { s_bin = j; s_total = sj; }
        }
        __syncthreads();
        thr |= (unsigned)s_bin << 10;
        total = above + s_total;
        __syncthreads();
    }

    // ---- Pass 2: collect candidates >= thr
    if (tid == 0) s_cnt = 0;
    __syncthreads();
    for (int i = tid; i < M; i += NT) {
        unsigned u = mono(row[i]);
        if (u >= thr) {
            unsigned p = atomicAdd(&s_cnt, 1u);
            if (p < CAP)
                keys[p] = ((ull)u << 32) | (ull)(0xFFFFFFFFu - (unsigned)i);
        }
    }
    __syncthreads();
    unsigned n = s_cnt; if (n > CAP) n = CAP;
    for (int i = tid; i < CAP; i += NT)
        if (i >= (int)n) keys[i] = 0ull;
    __syncthreads();

    // ---- Bitonic sort CAP=2048, descending (score desc, index asc on ties)
    for (int size = 2; size <= CAP; size <<= 1) {
        for (int stride = size >> 1; stride > 0; stride >>= 1) {
            int i = 2 * tid - (tid & (stride - 1));
            int j = i + stride;
            bool desc = ((i & size) == 0);
            ull a = keys[i], c = keys[j];
            bool sw = desc ? (a < c) : (a > c);
            if (sw) { keys[i] = c; keys[j] = a; }
            __syncthreads();
        }
    }

    for (int k = tid; k < K_TOP; k += NT) {
        ull key = keys[k];
        unsigned u   = (unsigned)(key >> 32);
        unsigned idx = 0xFFFFFFFFu - (unsigned)(key & 0xFFFFFFFFu);
        out[SCORE_OFF + (size_t)b * K_TOP + k] = inv_mono(u);
        out[IDX_OFF   + (size_t)b * K_TOP + k] = (float)idx;
        g_topk_idx[b * K_TOP + k] = (int)idx;
    }
}

// ---------------------------------------------------------------------------
// Kernel 4: gather color_value rows for the selected indices
// ---------------------------------------------------------------------------
__global__ void gather_kernel(const float* __restrict__ cv, float* __restrict__ out) {
    int k = blockIdx.x;
    int b = blockIdx.y;
    int idx = g_topk_idx[b * K_TOP + k];
    const float4* src = (const float4*)(cv + (size_t)idx * D);
    float4* dst = (float4*)(out + ((size_t)b * K_TOP + k) * D);
    dst[threadIdx.x] = src[threadIdx.x];  // 128 threads x float4 = 512 floats
}

// ---------------------------------------------------------------------------
extern "C" void kernel_launch(void* const* d_in, const int* in_sizes, int n_in,
                              void* d_out, int out_size) {
    const float* q  = (const float*)d_in[0];  // query       [128, 512]
    const float* sk = (const float*)d_in[1];  // spatial_key [262144, 512]
    const float* cv = (const float*)d_in[2];  // color_value [262144, 512]
    float* out = (float*)d_out;

    normalize_kernel<<<B, 128>>>(q);
    gemm_kernel<<<M / TM, 256>>>(sk);
    topk_kernel<<<B, NT>>>(out);
    gather_kernel<<<dim3(K_TOP, B), 128>>>(cv, out);
}